// round 12
// baseline (speedup 1.0000x reference)
#include <cuda_runtime.h>
#include <math.h>

#define L 2048
#define DMOD 64
#define NH 4
#define DKV 16
#define NB 4
#define NEGV -1000000000.0f

typedef unsigned long long u64;
typedef unsigned int u32;

// scratch: projected Q/K/V head-major [b][h][l][16], context [b][l][64]
__device__ float g_Qp[NB*NH*L*DKV];
__device__ float g_Kp[NB*NH*L*DKV];
__device__ float g_Vp[NB*NH*L*DKV];
__device__ float g_ctx[NB*L*DMOD];

// ---- packed f32x2 helpers -------------------------------------------------
__device__ __forceinline__ u64 ffma2(u64 a, u64 b, u64 c) {
    u64 d; asm("fma.rn.f32x2 %0, %1, %2, %3;" : "=l"(d) : "l"(a), "l"(b), "l"(c));
    return d;
}
__device__ __forceinline__ u64 pack2(float x, float y) {
    u64 r; asm("mov.b64 %0, {%1, %2};" : "=l"(r) : "f"(x), "f"(y));
    return r;
}
__device__ __forceinline__ float2 unpack2(u64 a) {
    float2 v; asm("mov.b64 {%0, %1}, %2;" : "=f"(v.x), "=f"(v.y) : "l"(a));
    return v;
}
__device__ __forceinline__ u32 smem_u32(const void* p) {
    return (u32)__cvta_generic_to_shared(p);
}
__device__ __forceinline__ void cp16(u32 dst, const void* src) {
    asm volatile("cp.async.cg.shared.global [%0], [%1], 16;" :: "r"(dst), "l"(src));
}

// ---------------------------------------------------------------------------
// Projection: 1024 blocks x 8 rows, 1 row per warp (lane cp -> cols 2cp,2cp+1).
// 262K threads -> high occupancy hides weight-LDG latency.
// ---------------------------------------------------------------------------
__global__ void __launch_bounds__(256) proj_kernel(
    const float* __restrict__ inQ, const float* __restrict__ inK,
    const float* __restrict__ inV, const float* __restrict__ WQ,
    const float* __restrict__ WK, const float* __restrict__ WV)
{
    __shared__ float sx[3][8][DMOD];   // 6KB
    const int t = threadIdx.x;
    const int row0 = blockIdx.x * 8;

    if (t < 128) {   // stage 8 rows x 64 cols per array (128 float4 each)
        const int r = t >> 4, c4 = (t & 15) * 4;
        const size_t gidx = (size_t)(row0 + r)*DMOD + c4;
        *(float4*)&sx[0][r][c4] = *(const float4*)(inQ + gidx);
        *(float4*)&sx[1][r][c4] = *(const float4*)(inK + gidx);
        *(float4*)&sx[2][r][c4] = *(const float4*)(inV + gidx);
    }
    __syncthreads();

    const int cp = t & 31, r = t >> 5;   // warp r owns row r
    const u64* __restrict__ wq2 = (const u64*)WQ;
    const u64* __restrict__ wk2 = (const u64*)WK;
    const u64* __restrict__ wv2 = (const u64*)WV;

    u64 aq = 0ull, ak = 0ull, av = 0ull;
    #pragma unroll 8
    for (int e = 0; e < DMOD; e++) {
        const float xq = sx[0][r][e], xk = sx[1][r][e], xv = sx[2][r][e];
        aq = ffma2(pack2(xq, xq), __ldg(&wq2[e*32 + cp]), aq);
        ak = ffma2(pack2(xk, xk), __ldg(&wk2[e*32 + cp]), ak);
        av = ffma2(pack2(xv, xv), __ldg(&wv2[e*32 + cp]), av);
    }

    const int row = row0 + r;
    const int b = row >> 11, l = row & (L-1);
    const int c0 = cp * 2;
    const int h = c0 >> 4, d = c0 & 15;
    const size_t o = (((size_t)b*NH + h)*L + l)*DKV + d;
    *(u64*)&g_Qp[o] = aq;
    *(u64*)&g_Kp[o] = ak;
    *(u64*)&g_Vp[o] = av;
}

// ---------------------------------------------------------------------------
// Attention. Block = 128 thr, (bh, 64-query tile). Thread: 4 queries
// (g = t>>3), 8 CONTIGUOUS keys [8j, 8j+8) (j = t&7) -> vectorized gmem IO.
// Pipeline structure IDENTICAL to the proven 214.5us kernel:
//   STAGE(next) -> wait_group 1 -> sync -> compute -> sync.
// New vs that kernel: res+mask for the whole iteration prefetched at loop
// top so their DRAM latency is covered by the QK FFMA2 stream.
// Simple softmax (scores bounded). launch_bounds(128,2): no spills.
// ---------------------------------------------------------------------------
__global__ void __launch_bounds__(128, 2) attn_kernel(
    const float* __restrict__ res_att,
    const unsigned char* __restrict__ mask,
    float* __restrict__ scores)
{
    const int bh = blockIdx.y;
    const int b  = bh >> 2, h = bh & 3;
    const int q0 = blockIdx.x * 64;
    const int t  = threadIdx.x;
    const int j  = t & 7;
    const int g  = t >> 3;
    const int qg0 = q0 + g * 4;

    __shared__ float sK[2][64][20];
    __shared__ float sV[2][64][20];

    // staging geometry (constant per thread)
    const int c0s = t,        r0s = c0s >> 2, e0s = (c0s & 3) * 4;
    const int c1s = t + 128,  r1s = c1s >> 2, e1s = (c1s & 3) * 4;
    const int p0 = (r0s & 7) * 8 + (r0s >> 3);   // gmem key for smem row r0s
    const int p1 = (r1s & 7) * 8 + (r1s >> 3);
    const u32 skb = smem_u32(&sK[0][0][0]);
    const u32 svb = smem_u32(&sV[0][0][0]);
    const u32 BUFB = 64*20*4;
    const u32 dK0a = skb + (u32)(r0s*80 + e0s*4), dK1a = skb + (u32)(r1s*80 + e1s*4);
    const u32 dV0a = svb + (u32)(r0s*80 + e0s*4), dV1a = svb + (u32)(r1s*80 + e1s*4);
    const u32 dK0b = dK0a + BUFB, dK1b = dK1a + BUFB;
    const u32 dV0b = dV0a + BUFB, dV1b = dV1a + BUFB;
    const float* gKb = g_Kp + ((size_t)bh*L)*DKV;
    const float* gVb = g_Vp + ((size_t)bh*L)*DKV;
    #define STAGE(buf, kt) do {                                           \
        const u32 _dK0 = (buf) ? dK0b : dK0a;                             \
        const u32 _dK1 = (buf) ? dK1b : dK1a;                             \
        const u32 _dV0 = (buf) ? dV0b : dV0a;                             \
        const u32 _dV1 = (buf) ? dV1b : dV1a;                             \
        cp16(_dK0, gKb + ((kt) + p0)*DKV + e0s);                          \
        cp16(_dK1, gKb + ((kt) + p1)*DKV + e1s);                          \
        cp16(_dV0, gVb + ((kt) + p0)*DKV + e0s);                          \
        cp16(_dV1, gVb + ((kt) + p1)*DKV + e1s);                          \
        asm volatile("cp.async.commit_group;");                           \
    } while (0)

    // 4 query rows -> packed register pairs
    u64 qp[4][8];
    #pragma unroll
    for (int q = 0; q < 4; q++) {
        const ulonglong2* Qrow = (const ulonglong2*)(g_Qp + ((size_t)bh*L + qg0 + q)*DKV);
        #pragma unroll
        for (int e = 0; e < 4; e++) {
            ulonglong2 v = Qrow[e];
            qp[q][2*e] = v.x; qp[q][2*e+1] = v.y;
        }
    }

    const float*         res0 = res_att + ((size_t)bh*L + qg0)*L + j*8;
    const unsigned char* msk0 = mask    + ((size_t)b *L + qg0)*L + j*8;
    float*               scr0 = scores  + ((size_t)bh*L + qg0)*L + j*8;

    float psum[4];
    u64 acc[4][8];
    #pragma unroll
    for (int q = 0; q < 4; q++) {
        psum[q] = 0.f;
        #pragma unroll
        for (int d8 = 0; d8 < 8; d8++) acc[q][d8] = 0ull;
    }

    STAGE(0, 0);

    for (int it = 0; it < 32; it++) {
        const int kt = it * 64;
        if (it < 31) {
            STAGE((it+1) & 1, kt + 64);
            asm volatile("cp.async.wait_group 1;");
        } else {
            asm volatile("cp.async.wait_group 0;");
        }
        __syncthreads();

        // prefetch the whole iteration's res + mask (latency covered by QK below)
        float rr[2][4][4];
        u32 mlo[4], mhi[4];
        #pragma unroll
        for (int q = 0; q < 4; q++) {
            const float4 rv0 = *(const float4*)(res0 + (size_t)q*L + kt);
            const float4 rv1 = *(const float4*)(res0 + (size_t)q*L + kt + 4);
            rr[0][q][0] = rv0.x; rr[0][q][1] = rv0.y; rr[0][q][2] = rv0.z; rr[0][q][3] = rv0.w;
            rr[1][q][0] = rv1.x; rr[1][q][1] = rv1.y; rr[1][q][2] = rv1.z; rr[1][q][3] = rv1.w;
            const u64 mv = *(const u64*)(msk0 + (size_t)q*L + kt);
            mlo[q] = (u32)mv; mhi[q] = (u32)(mv >> 32);
        }

        const float* sKb_ = &sK[it & 1][0][0];
        const float* sVb_ = &sV[it & 1][0][0];

        #pragma unroll
        for (int half = 0; half < 2; half++) {
            #pragma unroll
            for (int i2 = 0; i2 < 4; i2++) {
                const int ii = half*4 + i2;
                const ulonglong2* kp = (const ulonglong2*)(sKb_ + (ii*8 + j)*20);
                const ulonglong2 k01 = kp[0], k23 = kp[1];
                float sv[4];
                #pragma unroll
                for (int q = 0; q < 4; q++) {
                    u64 a2 = ffma2(qp[q][0], k01.x, 0ull);
                    a2 = ffma2(qp[q][1], k01.y, a2);
                    a2 = ffma2(qp[q][2], k23.x, a2);
                    a2 = ffma2(qp[q][3], k23.y, a2);
                    u64 b2 = ffma2(qp[q][4], kp[2].x, 0ull);
                    b2 = ffma2(qp[q][5], kp[2].y, b2);
                    b2 = ffma2(qp[q][6], kp[3].x, b2);
                    b2 = ffma2(qp[q][7], kp[3].y, b2);
                    const float2 ua = unpack2(a2);
                    const float2 ub = unpack2(b2);
                    float s = fmaf((ua.x + ub.x) + (ua.y + ub.y), 0.25f, rr[half][q][i2]);
                    const u32 mm = half ? mhi[q] : mlo[q];
                    if (mm & (0xffu << (8*i2))) s = NEGV;
                    rr[half][q][i2] = s;
                    sv[q] = s;
                }
                const ulonglong2* vp = (const ulonglong2*)(sVb_ + (ii*8 + j)*20);
                const ulonglong2 v01 = vp[0], v23 = vp[1];
                #pragma unroll
                for (int q = 0; q < 4; q++) {
                    const float p = __expf(sv[q]);
                    psum[q] += p;
                    const u64 p2 = pack2(p, p);
                    acc[q][0] = ffma2(p2, v01.x, acc[q][0]);
                    acc[q][1] = ffma2(p2, v01.y, acc[q][1]);
                    acc[q][2] = ffma2(p2, v23.x, acc[q][2]);
                    acc[q][3] = ffma2(p2, v23.y, acc[q][3]);
                    acc[q][4] = ffma2(p2, vp[2].x, acc[q][4]);
                    acc[q][5] = ffma2(p2, vp[2].y, acc[q][5]);
                    acc[q][6] = ffma2(p2, vp[3].x, acc[q][6]);
                    acc[q][7] = ffma2(p2, vp[3].y, acc[q][7]);
                }
            }
            // write masked scores (coalesced STG.128)
            #pragma unroll
            for (int q = 0; q < 4; q++) {
                float4 ov;
                ov.x = rr[half][q][0]; ov.y = rr[half][q][1];
                ov.z = rr[half][q][2]; ov.w = rr[half][q][3];
                *(float4*)(scr0 + (size_t)q*L + kt + half*4) = ov;
            }
        }
        __syncthreads();   // protect buffer (it+1 stage target) reuse
    }

    // reduce across the 8 j-lanes; lane j==0 writes the context row
    #pragma unroll
    for (int q = 0; q < 4; q++) {
        float vals[16];
        #pragma unroll
        for (int d8 = 0; d8 < 8; d8++) {
            const float2 u = unpack2(acc[q][d8]);
            vals[2*d8] = u.x; vals[2*d8+1] = u.y;
        }
        float ls = psum[q];
        #pragma unroll
        for (int w = 4; w >= 1; w >>= 1) ls += __shfl_xor_sync(0xffffffffu, ls, w);
        #pragma unroll
        for (int d = 0; d < 16; d++) {
            #pragma unroll
            for (int w = 4; w >= 1; w >>= 1)
                vals[d] += __shfl_xor_sync(0xffffffffu, vals[d], w);
        }
        if (j == 0) {
            const float inv = 1.f / ls;
            float* crow = g_ctx + ((size_t)b*L + qg0 + q)*DMOD + h*DKV;
            #pragma unroll
            for (int d8 = 0; d8 < 4; d8++) {
                float4 o;
                o.x = vals[4*d8+0]*inv; o.y = vals[4*d8+1]*inv;
                o.z = vals[4*d8+2]*inv; o.w = vals[4*d8+3]*inv;
                *(float4*)&crow[4*d8] = o;
            }
        }
    }
}

// ---------------------------------------------------------------------------
// Epilogue: out = LayerNorm(ctx @ W_fc + input_Q). 256 blocks x 32 rows,
// thread = 2 cols x 4 rows; each warp owns 4 full rows -> warp-level LN.
// ---------------------------------------------------------------------------
__global__ void __launch_bounds__(256) epilogue_kernel(
    const float* __restrict__ inQ, const float* __restrict__ Wfc,
    float* __restrict__ out)
{
    __shared__ float sx[32][DMOD];   // ctx tile, 8KB
    const int t = threadIdx.x;
    const int row0 = blockIdx.x * 32;

    #pragma unroll
    for (int k = 0; k < 2; k++) {
        const int fl = t + k*256;
        const int r = fl >> 4, c4 = (fl & 15) * 4;
        *(float4*)&sx[r][c4] = *(const float4*)(g_ctx + (size_t)(row0 + r)*DMOD + c4);
    }
    __syncthreads();

    const int cp = t & 31, rsub = t >> 5;
    const int c0 = cp * 2;
    const u64* __restrict__ w2 = (const u64*)Wfc;

    u64 y[4];
    #pragma unroll
    for (int r = 0; r < 4; r++)
        y[r] = *(const u64*)(inQ + (size_t)(row0 + rsub*4 + r)*DMOD + c0);

    #pragma unroll 4
    for (int e4 = 0; e4 < DMOD; e4 += 4) {
        float4 xr[4];
        #pragma unroll
        for (int r = 0; r < 4; r++) xr[r] = *(const float4*)&sx[rsub*4 + r][e4];
        #pragma unroll
        for (int e = 0; e < 4; e++) {
            const u64 w = __ldg(&w2[(e4+e)*32 + cp]);
            #pragma unroll
            for (int r = 0; r < 4; r++) {
                const float x = (&xr[r].x)[e];
                y[r] = ffma2(pack2(x, x), w, y[r]);
            }
        }
    }

    #pragma unroll
    for (int r = 0; r < 4; r++) {
        const float2 u = unpack2(y[r]);
        float s1 = u.x + u.y;
        float s2 = u.x*u.x + u.y*u.y;
        #pragma unroll
        for (int wd = 16; wd >= 1; wd >>= 1) {
            s1 += __shfl_xor_sync(0xffffffffu, s1, wd);
            s2 += __shfl_xor_sync(0xffffffffu, s2, wd);
        }
        const float mu  = s1 * (1.f/64.f);
        const float var = s2 * (1.f/64.f) - mu*mu;
        const float rs  = rsqrtf(var + 1e-5f);
        const int row = row0 + rsub*4 + r;
        *(u64*)(out + (size_t)row*DMOD + c0) = pack2((u.x - mu)*rs, (u.y - mu)*rs);
    }
}

// ---------------------------------------------------------------------------
extern "C" void kernel_launch(void* const* d_in, const int* in_sizes, int n_in,
                              void* d_out, int out_size)
{
    const float*         inQ  = (const float*)d_in[0];
    const float*         inK  = (const float*)d_in[1];
    const float*         inV  = (const float*)d_in[2];
    const unsigned char* mask = (const unsigned char*)d_in[3];
    const float*         res  = (const float*)d_in[4];
    const float*         WQ   = (const float*)d_in[5];
    const float*         WK   = (const float*)d_in[6];
    const float*         WV   = (const float*)d_in[7];
    const float*         Wfc  = (const float*)d_in[8];

    float* out    = (float*)d_out;
    float* scores = out + (size_t)NB * L * DMOD;   // tuple order: (out, scores)

    proj_kernel<<<(NB*L)/8, 256>>>(inQ, inK, inV, WQ, WK, WV);
    attn_kernel<<<dim3(L/64, NB*NH), 128>>>(res, mask, scores);
    epilogue_kernel<<<(NB*L)/32, 256>>>(inQ, Wfc, out);
}

// round 13
// speedup vs baseline: 1.1045x; 1.1045x over previous
#include <cuda_runtime.h>
#include <math.h>

#define L 2048
#define DMOD 64
#define NH 4
#define DKV 16
#define NB 4
#define NEGV -1000000000.0f

typedef unsigned long long u64;
typedef unsigned int u32;

// scratch: projected Q/K/V head-major [b][h][l][16], context [b][l][64]
__device__ float g_Qp[NB*NH*L*DKV];
__device__ float g_Kp[NB*NH*L*DKV];
__device__ float g_Vp[NB*NH*L*DKV];
__device__ float g_ctx[NB*L*DMOD];

// ---- packed f32x2 helpers -------------------------------------------------
__device__ __forceinline__ u64 ffma2(u64 a, u64 b, u64 c) {
    u64 d; asm("fma.rn.f32x2 %0, %1, %2, %3;" : "=l"(d) : "l"(a), "l"(b), "l"(c));
    return d;
}
__device__ __forceinline__ u64 pack2(float x, float y) {
    u64 r; asm("mov.b64 %0, {%1, %2};" : "=l"(r) : "f"(x), "f"(y));
    return r;
}
__device__ __forceinline__ float2 unpack2(u64 a) {
    float2 v; asm("mov.b64 {%0, %1}, %2;" : "=f"(v.x), "=f"(v.y) : "l"(a));
    return v;
}
__device__ __forceinline__ u32 smem_u32(const void* p) {
    return (u32)__cvta_generic_to_shared(p);
}
__device__ __forceinline__ void cp16(u32 dst, const void* src) {
    asm volatile("cp.async.cg.shared.global [%0], [%1], 16;" :: "r"(dst), "l"(src));
}

// ---------------------------------------------------------------------------
// Projection: 512 blocks x 16 rows, 128 thr. Thread: 4 rows x 2 cols ->
// 48 weight-LDG per row (4x reuse) AND ~5 CTAs/SM (20 warps) for latency
// hiding. Weights as coalesced LDG.64 (L1-resident), FFMA2 accumulators.
// ---------------------------------------------------------------------------
__global__ void __launch_bounds__(128) proj_kernel(
    const float* __restrict__ inQ, const float* __restrict__ inK,
    const float* __restrict__ inV, const float* __restrict__ WQ,
    const float* __restrict__ WK, const float* __restrict__ WV)
{
    __shared__ float sx[3][16][DMOD];   // 12KB
    const int t = threadIdx.x;
    const int row0 = blockIdx.x * 16;

    #pragma unroll
    for (int k = 0; k < 2; k++) {       // stage 16 rows x 64 cols per array
        const int fl = t + k*128;
        const int r = fl >> 4, c4 = (fl & 15) * 4;
        const size_t gidx = (size_t)(row0 + r)*DMOD + c4;
        *(float4*)&sx[0][r][c4] = *(const float4*)(inQ + gidx);
        *(float4*)&sx[1][r][c4] = *(const float4*)(inK + gidx);
        *(float4*)&sx[2][r][c4] = *(const float4*)(inV + gidx);
    }
    __syncthreads();

    const int cp = t & 31, rsub = t >> 5;   // rsub 0..3 -> rows rsub*4..+3
    const u64* __restrict__ wq2 = (const u64*)WQ;
    const u64* __restrict__ wk2 = (const u64*)WK;
    const u64* __restrict__ wv2 = (const u64*)WV;

    u64 aq[4], ak[4], av[4];
    #pragma unroll
    for (int r = 0; r < 4; r++) { aq[r] = 0ull; ak[r] = 0ull; av[r] = 0ull; }

    #pragma unroll 4
    for (int e4 = 0; e4 < DMOD; e4 += 4) {
        float4 xq[4], xk[4], xv[4];
        #pragma unroll
        for (int r = 0; r < 4; r++) {
            xq[r] = *(const float4*)&sx[0][rsub*4 + r][e4];
            xk[r] = *(const float4*)&sx[1][rsub*4 + r][e4];
            xv[r] = *(const float4*)&sx[2][rsub*4 + r][e4];
        }
        #pragma unroll
        for (int e = 0; e < 4; e++) {
            const u64 wq = __ldg(&wq2[(e4+e)*32 + cp]);
            const u64 wk = __ldg(&wk2[(e4+e)*32 + cp]);
            const u64 wv = __ldg(&wv2[(e4+e)*32 + cp]);
            #pragma unroll
            for (int r = 0; r < 4; r++) {
                const float q = (&xq[r].x)[e], kk = (&xk[r].x)[e], vv = (&xv[r].x)[e];
                aq[r] = ffma2(pack2(q, q), wq, aq[r]);
                ak[r] = ffma2(pack2(kk, kk), wk, ak[r]);
                av[r] = ffma2(pack2(vv, vv), wv, av[r]);
            }
        }
    }

    const int c0 = cp * 2;
    const int h = c0 >> 4, d = c0 & 15;
    #pragma unroll
    for (int r = 0; r < 4; r++) {
        const int row = row0 + rsub*4 + r;
        const int b = row >> 11, l = row & (L-1);
        const size_t o = (((size_t)b*NH + h)*L + l)*DKV + d;
        *(u64*)&g_Qp[o] = aq[r];
        *(u64*)&g_Kp[o] = ak[r];
        *(u64*)&g_Vp[o] = av[r];
    }
}

// ---------------------------------------------------------------------------
// Attention — EXACT structure of the proven 214.5us kernel (R8).
// Block = 128 thr, (bh, 64-query tile). Thread: 4 queries x 8 contiguous
// keys. cp.async double-buffer; permuted smem rows; simple softmax;
// launch_bounds(128,2): 256-reg cap, no spills.
// ---------------------------------------------------------------------------
__global__ void __launch_bounds__(128, 2) attn_kernel(
    const float* __restrict__ res_att,
    const unsigned char* __restrict__ mask,
    float* __restrict__ scores)
{
    const int bh = blockIdx.y;
    const int b  = bh >> 2, h = bh & 3;
    const int q0 = blockIdx.x * 64;
    const int t  = threadIdx.x;
    const int j  = t & 7;
    const int g  = t >> 3;
    const int qg0 = q0 + g * 4;

    __shared__ float sK[2][64][20];
    __shared__ float sV[2][64][20];

    // staging geometry (constant per thread)
    const int c0s = t,        r0s = c0s >> 2, e0s = (c0s & 3) * 4;
    const int c1s = t + 128,  r1s = c1s >> 2, e1s = (c1s & 3) * 4;
    const int p0 = (r0s & 7) * 8 + (r0s >> 3);   // gmem key for smem row r0s
    const int p1 = (r1s & 7) * 8 + (r1s >> 3);
    const u32 skb = smem_u32(&sK[0][0][0]);
    const u32 svb = smem_u32(&sV[0][0][0]);
    const u32 BUFB = 64*20*4;
    const u32 dK0a = skb + (u32)(r0s*80 + e0s*4), dK1a = skb + (u32)(r1s*80 + e1s*4);
    const u32 dV0a = svb + (u32)(r0s*80 + e0s*4), dV1a = svb + (u32)(r1s*80 + e1s*4);
    const u32 dK0b = dK0a + BUFB, dK1b = dK1a + BUFB;
    const u32 dV0b = dV0a + BUFB, dV1b = dV1a + BUFB;
    const float* gKb = g_Kp + ((size_t)bh*L)*DKV;
    const float* gVb = g_Vp + ((size_t)bh*L)*DKV;
    #define STAGE(buf, kt) do {                                           \
        const u32 _dK0 = (buf) ? dK0b : dK0a;                             \
        const u32 _dK1 = (buf) ? dK1b : dK1a;                             \
        const u32 _dV0 = (buf) ? dV0b : dV0a;                             \
        const u32 _dV1 = (buf) ? dV1b : dV1a;                             \
        cp16(_dK0, gKb + ((kt) + p0)*DKV + e0s);                          \
        cp16(_dK1, gKb + ((kt) + p1)*DKV + e1s);                          \
        cp16(_dV0, gVb + ((kt) + p0)*DKV + e0s);                          \
        cp16(_dV1, gVb + ((kt) + p1)*DKV + e1s);                          \
        asm volatile("cp.async.commit_group;");                           \
    } while (0)

    // 4 query rows -> packed register pairs
    u64 qp[4][8];
    #pragma unroll
    for (int q = 0; q < 4; q++) {
        const ulonglong2* Qrow = (const ulonglong2*)(g_Qp + ((size_t)bh*L + qg0 + q)*DKV);
        #pragma unroll
        for (int e = 0; e < 4; e++) {
            ulonglong2 v = Qrow[e];
            qp[q][2*e] = v.x; qp[q][2*e+1] = v.y;
        }
    }

    const float*         res0 = res_att + ((size_t)bh*L + qg0)*L + j*8;
    const unsigned char* msk0 = mask    + ((size_t)b *L + qg0)*L + j*8;
    float*               scr0 = scores  + ((size_t)bh*L + qg0)*L + j*8;

    float psum[4];
    u64 acc[4][8];
    #pragma unroll
    for (int q = 0; q < 4; q++) {
        psum[q] = 0.f;
        #pragma unroll
        for (int d8 = 0; d8 < 8; d8++) acc[q][d8] = 0ull;
    }

    STAGE(0, 0);

    for (int it = 0; it < 32; it++) {
        const int kt = it * 64;
        if (it < 31) {
            STAGE((it+1) & 1, kt + 64);
            asm volatile("cp.async.wait_group 1;");
        } else {
            asm volatile("cp.async.wait_group 0;");
        }
        __syncthreads();

        const float* sKb_ = &sK[it & 1][0][0];
        const float* sVb_ = &sV[it & 1][0][0];

        #pragma unroll
        for (int half = 0; half < 2; half++) {
            // res tile (overwritten with the masked score) + mask
            float rr[4][4];
            u32 mu[4];
            #pragma unroll
            for (int q = 0; q < 4; q++) {
                const float4 rv = *(const float4*)(res0 + (size_t)q*L + kt + half*4);
                rr[q][0] = rv.x; rr[q][1] = rv.y; rr[q][2] = rv.z; rr[q][3] = rv.w;
                mu[q] = *(const u32*)(msk0 + (size_t)q*L + kt + half*4);
            }
            #pragma unroll
            for (int i2 = 0; i2 < 4; i2++) {
                const int ii = half*4 + i2;
                const ulonglong2* kp = (const ulonglong2*)(sKb_ + (ii*8 + j)*20);
                const ulonglong2 k01 = kp[0], k23 = kp[1];
                float sv[4];
                #pragma unroll
                for (int q = 0; q < 4; q++) {
                    u64 a2 = ffma2(qp[q][0], k01.x, 0ull);
                    a2 = ffma2(qp[q][1], k01.y, a2);
                    a2 = ffma2(qp[q][2], k23.x, a2);
                    a2 = ffma2(qp[q][3], k23.y, a2);
                    u64 b2 = ffma2(qp[q][4], kp[2].x, 0ull);
                    b2 = ffma2(qp[q][5], kp[2].y, b2);
                    b2 = ffma2(qp[q][6], kp[3].x, b2);
                    b2 = ffma2(qp[q][7], kp[3].y, b2);
                    const float2 ua = unpack2(a2);
                    const float2 ub = unpack2(b2);
                    float s = fmaf((ua.x + ub.x) + (ua.y + ub.y), 0.25f, rr[q][i2]);
                    if (mu[q] & (0xffu << (8*i2))) s = NEGV;
                    rr[q][i2] = s;
                    sv[q] = s;
                }
                const ulonglong2* vp = (const ulonglong2*)(sVb_ + (ii*8 + j)*20);
                const ulonglong2 v01 = vp[0], v23 = vp[1];
                #pragma unroll
                for (int q = 0; q < 4; q++) {
                    const float p = __expf(sv[q]);
                    psum[q] += p;
                    const u64 p2 = pack2(p, p);
                    acc[q][0] = ffma2(p2, v01.x, acc[q][0]);
                    acc[q][1] = ffma2(p2, v01.y, acc[q][1]);
                    acc[q][2] = ffma2(p2, v23.x, acc[q][2]);
                    acc[q][3] = ffma2(p2, v23.y, acc[q][3]);
                    acc[q][4] = ffma2(p2, vp[2].x, acc[q][4]);
                    acc[q][5] = ffma2(p2, vp[2].y, acc[q][5]);
                    acc[q][6] = ffma2(p2, vp[3].x, acc[q][6]);
                    acc[q][7] = ffma2(p2, vp[3].y, acc[q][7]);
                }
            }
            // write masked scores (coalesced STG.128)
            #pragma unroll
            for (int q = 0; q < 4; q++) {
                float4 ov;
                ov.x = rr[q][0]; ov.y = rr[q][1]; ov.z = rr[q][2]; ov.w = rr[q][3];
                *(float4*)(scr0 + (size_t)q*L + kt + half*4) = ov;
            }
        }
        __syncthreads();   // protect buffer (it+1 stage target) reuse
    }

    // reduce across the 8 j-lanes; lane j==0 writes the context row
    #pragma unroll
    for (int q = 0; q < 4; q++) {
        float vals[16];
        #pragma unroll
        for (int d8 = 0; d8 < 8; d8++) {
            const float2 u = unpack2(acc[q][d8]);
            vals[2*d8] = u.x; vals[2*d8+1] = u.y;
        }
        float ls = psum[q];
        #pragma unroll
        for (int w = 4; w >= 1; w >>= 1) ls += __shfl_xor_sync(0xffffffffu, ls, w);
        #pragma unroll
        for (int d = 0; d < 16; d++) {
            #pragma unroll
            for (int w = 4; w >= 1; w >>= 1)
                vals[d] += __shfl_xor_sync(0xffffffffu, vals[d], w);
        }
        if (j == 0) {
            const float inv = 1.f / ls;
            float* crow = g_ctx + ((size_t)b*L + qg0 + q)*DMOD + h*DKV;
            #pragma unroll
            for (int d8 = 0; d8 < 4; d8++) {
                float4 o;
                o.x = vals[4*d8+0]*inv; o.y = vals[4*d8+1]*inv;
                o.z = vals[4*d8+2]*inv; o.w = vals[4*d8+3]*inv;
                *(float4*)&crow[4*d8] = o;
            }
        }
    }
}

// ---------------------------------------------------------------------------
// Epilogue: out = LayerNorm(ctx @ W_fc + input_Q). 256 blocks x 32 rows,
// thread = 2 cols x 4 rows; each warp owns 4 full rows -> warp-level LN.
// ---------------------------------------------------------------------------
__global__ void __launch_bounds__(256) epilogue_kernel(
    const float* __restrict__ inQ, const float* __restrict__ Wfc,
    float* __restrict__ out)
{
    __shared__ float sx[32][DMOD];   // ctx tile, 8KB
    const int t = threadIdx.x;
    const int row0 = blockIdx.x * 32;

    #pragma unroll
    for (int k = 0; k < 2; k++) {
        const int fl = t + k*256;
        const int r = fl >> 4, c4 = (fl & 15) * 4;
        *(float4*)&sx[r][c4] = *(const float4*)(g_ctx + (size_t)(row0 + r)*DMOD + c4);
    }
    __syncthreads();

    const int cp = t & 31, rsub = t >> 5;
    const int c0 = cp * 2;
    const u64* __restrict__ w2 = (const u64*)Wfc;

    u64 y[4];
    #pragma unroll
    for (int r = 0; r < 4; r++)
        y[r] = *(const u64*)(inQ + (size_t)(row0 + rsub*4 + r)*DMOD + c0);

    #pragma unroll 4
    for (int e4 = 0; e4 < DMOD; e4 += 4) {
        float4 xr[4];
        #pragma unroll
        for (int r = 0; r < 4; r++) xr[r] = *(const float4*)&sx[rsub*4 + r][e4];
        #pragma unroll
        for (int e = 0; e < 4; e++) {
            const u64 w = __ldg(&w2[(e4+e)*32 + cp]);
            #pragma unroll
            for (int r = 0; r < 4; r++) {
                const float x = (&xr[r].x)[e];
                y[r] = ffma2(pack2(x, x), w, y[r]);
            }
        }
    }

    #pragma unroll
    for (int r = 0; r < 4; r++) {
        const float2 u = unpack2(y[r]);
        float s1 = u.x + u.y;
        float s2 = u.x*u.x + u.y*u.y;
        #pragma unroll
        for (int wd = 16; wd >= 1; wd >>= 1) {
            s1 += __shfl_xor_sync(0xffffffffu, s1, wd);
            s2 += __shfl_xor_sync(0xffffffffu, s2, wd);
        }
        const float mu  = s1 * (1.f/64.f);
        const float var = s2 * (1.f/64.f) - mu*mu;
        const float rs  = rsqrtf(var + 1e-5f);
        const int row = row0 + rsub*4 + r;
        *(u64*)(out + (size_t)row*DMOD + c0) = pack2((u.x - mu)*rs, (u.y - mu)*rs);
    }
}

// ---------------------------------------------------------------------------
extern "C" void kernel_launch(void* const* d_in, const int* in_sizes, int n_in,
                              void* d_out, int out_size)
{
    const float*         inQ  = (const float*)d_in[0];
    const float*         inK  = (const float*)d_in[1];
    const float*         inV  = (const float*)d_in[2];
    const unsigned char* mask = (const unsigned char*)d_in[3];
    const float*         res  = (const float*)d_in[4];
    const float*         WQ   = (const float*)d_in[5];
    const float*         WK   = (const float*)d_in[6];
    const float*         WV   = (const float*)d_in[7];
    const float*         Wfc  = (const float*)d_in[8];

    float* out    = (float*)d_out;
    float* scores = out + (size_t)NB * L * DMOD;   // tuple order: (out, scores)

    proj_kernel<<<(NB*L)/16, 128>>>(inQ, inK, inV, WQ, WK, WV);
    attn_kernel<<<dim3(L/64, NB*NH), 128>>>(res, mask, scores);
    epilogue_kernel<<<(NB*L)/32, 256>>>(inQ, Wfc, out);
}